// round 2
// baseline (speedup 1.0000x reference)
#include <cuda_runtime.h>
#include <cuda_fp16.h>

#define N_NODES 10000
#define N_EDGES 640000
#define K_DIM   128

// ---------------- scratch ------------------------------------------------------
__device__ __align__(128) int    g_deg[N_NODES];
__device__ __align__(128) int    g_off[N_NODES + 1];
__device__ __align__(128) int    g_pos[N_NODES];
__device__ __align__(128) int    g_csr[N_EDGES];
__device__ __align__(128) __half g_yn[N_NODES * 128];   // neighbor projections (fp16)
__device__ __align__(128) float  g_ys[N_NODES * 128];   // self projections (fp32)
__device__ __align__(128) float  g_h0[N_NODES * 128];
__device__ __align__(128) float  g_h1[N_NODES * 128];

// ---------------- CSR build ----------------------------------------------------
__global__ void hist_k(const int* __restrict__ dst) {
    int e4 = blockIdx.x * blockDim.x + threadIdx.x;
    if (e4 * 4 < N_EDGES) {
        int4 d = ((const int4*)dst)[e4];
        atomicAdd(&g_deg[d.x], 1);
        atomicAdd(&g_deg[d.y], 1);
        atomicAdd(&g_deg[d.z], 1);
        atomicAdd(&g_deg[d.w], 1);
    }
}

__global__ void scan_k() {   // single block, 1024 threads, 10 elems/thread
    __shared__ int wsum[32];
    int t = threadIdx.x;
    int base = t * 10;
    int loc[10];
    int s = 0;
    #pragma unroll
    for (int i = 0; i < 10; i++) {
        int idx = base + i;
        int v = (idx < N_NODES) ? g_deg[idx] : 0;
        loc[i] = s; s += v;
    }
    int lane = t & 31, w = t >> 5;
    int x = s;
    #pragma unroll
    for (int o = 1; o < 32; o <<= 1) {
        int y = __shfl_up_sync(0xffffffff, x, o);
        if (lane >= o) x += y;
    }
    if (lane == 31) wsum[w] = x;
    __syncthreads();
    if (w == 0) {
        int y = wsum[lane];
        #pragma unroll
        for (int o = 1; o < 32; o <<= 1) {
            int z = __shfl_up_sync(0xffffffff, y, o);
            if (lane >= o) y += z;
        }
        wsum[lane] = y;
    }
    __syncthreads();
    int warp_excl = (w == 0) ? 0 : wsum[w - 1];
    int texcl = warp_excl + x - s;
    #pragma unroll
    for (int i = 0; i < 10; i++) {
        int idx = base + i;
        if (idx < N_NODES) {
            int o = texcl + loc[i];
            g_off[idx] = o; g_pos[idx] = o;
        }
    }
    if (t == 1023) g_off[N_NODES] = warp_excl + x;
}

__global__ void scatter_k(const int* __restrict__ src, const int* __restrict__ dst) {
    int e4 = blockIdx.x * blockDim.x + threadIdx.x;
    if (e4 * 4 < N_EDGES) {
        int4 s = ((const int4*)src)[e4];
        int4 d = ((const int4*)dst)[e4];
        g_csr[atomicAdd(&g_pos[d.x], 1)] = s.x;
        g_csr[atomicAdd(&g_pos[d.y], 1)] = s.y;
        g_csr[atomicAdd(&g_pos[d.z], 1)] = s.z;
        g_csr[atomicAdd(&g_pos[d.w], 1)] = s.w;
    }
}

// ---------------- fused dual GEMM with packed f32x2 FMA -------------------------
// Y = X @ [W_neigh | W_self]; neigh half stored fp16 (gathered later), self fp32.
// BM=128, BN=64, BK=16, 256 threads, each thread: 8 rows (as 4 packed pairs) x 4 cols.
template <int DOUT>
__global__ void gemm_dual_k(const float* __restrict__ X,
                            const float* __restrict__ Wn,
                            const float* __restrict__ Ws,
                            __half* __restrict__ Yn,
                            float*  __restrict__ Ys) {
    constexpr int BM = 128, BN = 64, BK = 16;
    constexpr int ASTRIDE = BM + 4;                 // pad: reduces STS conflicts
    __shared__ float As[BK][ASTRIDE];               // transposed A tile
    __shared__ float Bd[BK][BN * 2];                // B tile, each value duplicated

    const int tid  = threadIdx.x;
    const int row0 = blockIdx.x * BM;
    const int by   = blockIdx.y;
    const bool is_self = (by >= (DOUT / BN));
    const int col0 = (is_self ? (by - DOUT / BN) : by) * BN;
    const float* W = (is_self ? Ws : Wn) + col0;

    const int tx = tid & 15, ty = tid >> 4;

    unsigned long long accp[4][4];
    #pragma unroll
    for (int i = 0; i < 4; i++)
        #pragma unroll
        for (int j = 0; j < 4; j++) accp[i][j] = 0ULL;

    for (int k0 = 0; k0 < K_DIM; k0 += BK) {
        // A tile: 512 float4 loads, 2 per thread, stored transposed
        #pragma unroll
        for (int h = 0; h < 2; h++) {
            int f  = tid + h * 256;
            int r  = f >> 2;
            int kq = (f & 3) * 4;
            int gr = row0 + r;
            float4 av = make_float4(0.f, 0.f, 0.f, 0.f);
            if (gr < N_NODES)
                av = *(const float4*)(X + (size_t)gr * K_DIM + k0 + kq);
            As[kq + 0][r] = av.x; As[kq + 1][r] = av.y;
            As[kq + 2][r] = av.z; As[kq + 3][r] = av.w;
        }
        // B tile: 1 float4 per thread, store duplicated pairs
        {
            int bk = tid >> 4, bc = (tid & 15) * 4;
            float4 bv = *(const float4*)(W + (size_t)(k0 + bk) * DOUT + bc);
            float2* d = (float2*)&Bd[bk][bc * 2];
            d[0] = make_float2(bv.x, bv.x);
            d[1] = make_float2(bv.y, bv.y);
            d[2] = make_float2(bv.z, bv.z);
            d[3] = make_float2(bv.w, bv.w);
        }
        __syncthreads();

        #pragma unroll
        for (int k = 0; k < BK; k++) {
            unsigned long long a[4], b[4];
            const unsigned long long* ap =
                (const unsigned long long*)&As[k][ty * 8];
            a[0] = ap[0]; a[1] = ap[1]; a[2] = ap[2]; a[3] = ap[3];
            const unsigned long long* bp =
                (const unsigned long long*)&Bd[k][tx * 8];
            b[0] = bp[0]; b[1] = bp[1]; b[2] = bp[2]; b[3] = bp[3];
            #pragma unroll
            for (int i = 0; i < 4; i++)
                #pragma unroll
                for (int j = 0; j < 4; j++)
                    asm("fma.rn.f32x2 %0, %1, %2, %0;"
                        : "+l"(accp[i][j]) : "l"(a[i]), "l"(b[j]));
        }
        __syncthreads();
    }

    #pragma unroll
    for (int i = 0; i < 4; i++) {
        float2 v[4];
        #pragma unroll
        for (int j = 0; j < 4; j++) v[j] = *(float2*)&accp[i][j];
        int r0 = row0 + ty * 8 + 2 * i;
        if (is_self) {
            if (r0 < N_NODES)
                *(float4*)&Ys[(size_t)r0 * DOUT + col0 + tx * 4] =
                    make_float4(v[0].x, v[1].x, v[2].x, v[3].x);
            if (r0 + 1 < N_NODES)
                *(float4*)&Ys[(size_t)(r0 + 1) * DOUT + col0 + tx * 4] =
                    make_float4(v[0].y, v[1].y, v[2].y, v[3].y);
        } else {
            if (r0 < N_NODES) {
                __half2 h0 = __floats2half2_rn(v[0].x, v[1].x);
                __half2 h1 = __floats2half2_rn(v[2].x, v[3].x);
                uint2 u; u.x = *(unsigned*)&h0; u.y = *(unsigned*)&h1;
                *(uint2*)&Yn[(size_t)r0 * DOUT + col0 + tx * 4] = u;
            }
            if (r0 + 1 < N_NODES) {
                __half2 h0 = __floats2half2_rn(v[0].y, v[1].y);
                __half2 h1 = __floats2half2_rn(v[2].y, v[3].y);
                uint2 u; u.x = *(unsigned*)&h0; u.y = *(unsigned*)&h1;
                *(uint2*)&Yn[(size_t)(r0 + 1) * DOUT + col0 + tx * 4] = u;
            }
        }
    }
}

// ---------------- aggregate: out = relu?(mean(Yn[csr]) + Ys + bias) -------------
// One warp per node, fp16 gather, fp32 accumulation, 4-neighbor unroll.
template <int DOUT, bool RELU>
__global__ void aggregate_k(const __half* __restrict__ Yn,
                            const float*  __restrict__ Ys,
                            const float*  __restrict__ bias,
                            float*        __restrict__ out) {
    constexpr int V = DOUT / 32;                  // halves per lane: 4 or 2
    int gw = (blockIdx.x * blockDim.x + threadIdx.x) >> 5;
    if (gw >= N_NODES) return;
    int lane = threadIdx.x & 31;

    int beg = g_off[gw], end = g_off[gw + 1];
    float acc[V];
    #pragma unroll
    for (int v = 0; v < V; v++) acc[v] = 0.f;

    const __half* base = Yn + lane * V;
    int j = beg;
    if constexpr (V == 4) {
        for (; j + 4 <= end; j += 4) {
            int s0 = __ldg(&g_csr[j]);
            int s1 = __ldg(&g_csr[j + 1]);
            int s2 = __ldg(&g_csr[j + 2]);
            int s3 = __ldg(&g_csr[j + 3]);
            uint2 u0 = *(const uint2*)(base + (size_t)s0 * DOUT);
            uint2 u1 = *(const uint2*)(base + (size_t)s1 * DOUT);
            uint2 u2 = *(const uint2*)(base + (size_t)s2 * DOUT);
            uint2 u3 = *(const uint2*)(base + (size_t)s3 * DOUT);
            float2 a, b;
            a = __half22float2(*(__half2*)&u0.x); b = __half22float2(*(__half2*)&u0.y);
            acc[0] += a.x; acc[1] += a.y; acc[2] += b.x; acc[3] += b.y;
            a = __half22float2(*(__half2*)&u1.x); b = __half22float2(*(__half2*)&u1.y);
            acc[0] += a.x; acc[1] += a.y; acc[2] += b.x; acc[3] += b.y;
            a = __half22float2(*(__half2*)&u2.x); b = __half22float2(*(__half2*)&u2.y);
            acc[0] += a.x; acc[1] += a.y; acc[2] += b.x; acc[3] += b.y;
            a = __half22float2(*(__half2*)&u3.x); b = __half22float2(*(__half2*)&u3.y);
            acc[0] += a.x; acc[1] += a.y; acc[2] += b.x; acc[3] += b.y;
        }
        for (; j < end; j++) {
            int s0 = __ldg(&g_csr[j]);
            uint2 u0 = *(const uint2*)(base + (size_t)s0 * DOUT);
            float2 a = __half22float2(*(__half2*)&u0.x);
            float2 b = __half22float2(*(__half2*)&u0.y);
            acc[0] += a.x; acc[1] += a.y; acc[2] += b.x; acc[3] += b.y;
        }
    } else {
        for (; j + 4 <= end; j += 4) {
            int s0 = __ldg(&g_csr[j]);
            int s1 = __ldg(&g_csr[j + 1]);
            int s2 = __ldg(&g_csr[j + 2]);
            int s3 = __ldg(&g_csr[j + 3]);
            unsigned u0 = *(const unsigned*)(base + (size_t)s0 * DOUT);
            unsigned u1 = *(const unsigned*)(base + (size_t)s1 * DOUT);
            unsigned u2 = *(const unsigned*)(base + (size_t)s2 * DOUT);
            unsigned u3 = *(const unsigned*)(base + (size_t)s3 * DOUT);
            float2 a;
            a = __half22float2(*(__half2*)&u0); acc[0] += a.x; acc[1] += a.y;
            a = __half22float2(*(__half2*)&u1); acc[0] += a.x; acc[1] += a.y;
            a = __half22float2(*(__half2*)&u2); acc[0] += a.x; acc[1] += a.y;
            a = __half22float2(*(__half2*)&u3); acc[0] += a.x; acc[1] += a.y;
        }
        for (; j < end; j++) {
            int s0 = __ldg(&g_csr[j]);
            unsigned u0 = *(const unsigned*)(base + (size_t)s0 * DOUT);
            float2 a = __half22float2(*(__half2*)&u0);
            acc[0] += a.x; acc[1] += a.y;
        }
    }

    float inv = 1.0f / fmaxf((float)(end - beg), 1.0f);

    if constexpr (V == 4) {
        float4 s  = *(const float4*)(Ys + (size_t)gw * DOUT + lane * 4);
        float4 bb = *(const float4*)(bias + lane * 4);
        float4 o;
        o.x = acc[0] * inv + s.x + bb.x;
        o.y = acc[1] * inv + s.y + bb.y;
        o.z = acc[2] * inv + s.z + bb.z;
        o.w = acc[3] * inv + s.w + bb.w;
        if (RELU) {
            o.x = fmaxf(o.x, 0.f); o.y = fmaxf(o.y, 0.f);
            o.z = fmaxf(o.z, 0.f); o.w = fmaxf(o.w, 0.f);
        }
        *(float4*)(out + (size_t)gw * DOUT + lane * 4) = o;
    } else {
        float2 s  = *(const float2*)(Ys + (size_t)gw * DOUT + lane * 2);
        float2 bb = *(const float2*)(bias + lane * 2);
        float2 o;
        o.x = acc[0] * inv + s.x + bb.x;
        o.y = acc[1] * inv + s.y + bb.y;
        if (RELU) { o.x = fmaxf(o.x, 0.f); o.y = fmaxf(o.y, 0.f); }
        *(float2*)(out + (size_t)gw * DOUT + lane * 2) = o;
    }
}

// ---------------- launcher -------------------------------------------------------
extern "C" void kernel_launch(void* const* d_in, const int* in_sizes, int n_in,
                              void* d_out, int out_size) {
    const float* inputs  = (const float*)d_in[0];
    const float* W_self0 = (const float*)d_in[1];
    const float* W_nei0  = (const float*)d_in[2];
    const float* b0      = (const float*)d_in[3];
    const float* W_self1 = (const float*)d_in[4];
    const float* W_nei1  = (const float*)d_in[5];
    const float* b1      = (const float*)d_in[6];
    const float* W_self2 = (const float*)d_in[7];
    const float* W_nei2  = (const float*)d_in[8];
    const float* b2      = (const float*)d_in[9];
    const int* edge_src  = (const int*)d_in[10];
    const int* edge_dst  = (const int*)d_in[11];
    float* out = (float*)d_out;

    __half* yn; float *ys, *h0, *h1; int* deg;
    cudaGetSymbolAddress((void**)&yn,  g_yn);
    cudaGetSymbolAddress((void**)&ys,  g_ys);
    cudaGetSymbolAddress((void**)&h0,  g_h0);
    cudaGetSymbolAddress((void**)&h1,  g_h1);
    cudaGetSymbolAddress((void**)&deg, g_deg);

    // CSR build
    cudaMemsetAsync(deg, 0, N_NODES * sizeof(int));
    hist_k<<<(N_EDGES / 4 + 255) / 256, 256>>>(edge_dst);
    scan_k<<<1, 1024>>>();
    scatter_k<<<(N_EDGES / 4 + 255) / 256, 256>>>(edge_src, edge_dst);

    const int gm = (N_NODES + 127) / 128;        // 79
    const int agg_blocks = (N_NODES + 7) / 8;    // 1250 (8 warps/block)

    // layer 0: 128 -> 128, relu
    gemm_dual_k<128><<<dim3(gm, 4), 256>>>(inputs, W_nei0, W_self0, yn, ys);
    aggregate_k<128, true><<<agg_blocks, 256>>>(yn, ys, b0, h0);

    // layer 1: 128 -> 128, relu
    gemm_dual_k<128><<<dim3(gm, 4), 256>>>(h0, W_nei1, W_self1, yn, ys);
    aggregate_k<128, true><<<agg_blocks, 256>>>(yn, ys, b1, h1);

    // layer 2: 128 -> 64, no relu, straight to d_out
    gemm_dual_k<64><<<dim3(gm, 2), 256>>>(h1, W_nei2, W_self2, yn, ys);
    aggregate_k<64, false><<<agg_blocks, 256>>>(yn, ys, b2, out);

    (void)in_sizes; (void)n_in; (void)out_size;
}

// round 5
// speedup vs baseline: 1.4570x; 1.4570x over previous
#include <cuda_runtime.h>
#include <cuda_fp16.h>
#include <cstdint>

#define N_NODES 10000
#define N_EDGES 640000
#define K_DIM   128

// ---------------- scratch -------------------------------------------------------
__device__ __align__(128) int    g_deg[N_NODES];
__device__ __align__(128) int    g_off[N_NODES + 1];
__device__ __align__(128) int    g_pos[N_NODES];
__device__ __align__(128) int    g_csr[N_EDGES];
__device__ __align__(128) __half g_yn[N_NODES * 128];   // neighbor projections (fp16)
__device__ __align__(128) float  g_ys[N_NODES * 128];   // self projections (fp32)
__device__ __align__(128) float  g_h0[N_NODES * 128];
__device__ __align__(128) float  g_h1[N_NODES * 128];
__device__ __align__(128) __half g_bw[256 * 256];       // weights: [NOUT][hi128|lo128]

// ---------------- small PTX helpers (sm_80-era, safe on sm_103 target) ----------
__device__ __forceinline__ uint32_t smem_u32(const void* p) {
    uint32_t a;
    asm("{ .reg .u64 t; cvta.to.shared.u64 t, %1; cvt.u32.u64 %0, t; }" : "=r"(a) : "l"(p));
    return a;
}
__device__ __forceinline__ void ldsm_x4(uint32_t& r0, uint32_t& r1, uint32_t& r2,
                                        uint32_t& r3, uint32_t addr) {
    asm volatile("ldmatrix.sync.aligned.m8n8.x4.shared.b16 {%0,%1,%2,%3}, [%4];"
                 : "=r"(r0), "=r"(r1), "=r"(r2), "=r"(r3) : "r"(addr));
}
__device__ __forceinline__ void mma16816(float* d, uint32_t a0, uint32_t a1,
                                         uint32_t a2, uint32_t a3,
                                         uint32_t b0, uint32_t b1) {
    asm volatile(
        "mma.sync.aligned.m16n8k16.row.col.f32.f16.f16.f32 "
        "{%0,%1,%2,%3},{%4,%5,%6,%7},{%8,%9},{%0,%1,%2,%3};"
        : "+f"(d[0]), "+f"(d[1]), "+f"(d[2]), "+f"(d[3])
        : "r"(a0), "r"(a1), "r"(a2), "r"(a3), "r"(b0), "r"(b1));
}

// ---------------- CSR build ----------------------------------------------------
__global__ void hist_k(const int* __restrict__ dst) {
    int e4 = blockIdx.x * blockDim.x + threadIdx.x;
    if (e4 * 4 < N_EDGES) {
        int4 d = ((const int4*)dst)[e4];
        atomicAdd(&g_deg[d.x], 1); atomicAdd(&g_deg[d.y], 1);
        atomicAdd(&g_deg[d.z], 1); atomicAdd(&g_deg[d.w], 1);
    }
}

__global__ void scan_k() {
    __shared__ int wsum[32];
    int t = threadIdx.x;
    int base = t * 10;
    int loc[10];
    int s = 0;
    #pragma unroll
    for (int i = 0; i < 10; i++) {
        int idx = base + i;
        int v = (idx < N_NODES) ? g_deg[idx] : 0;
        loc[i] = s; s += v;
    }
    int lane = t & 31, w = t >> 5;
    int x = s;
    #pragma unroll
    for (int o = 1; o < 32; o <<= 1) {
        int y = __shfl_up_sync(0xffffffff, x, o);
        if (lane >= o) x += y;
    }
    if (lane == 31) wsum[w] = x;
    __syncthreads();
    if (w == 0) {
        int y = wsum[lane];
        #pragma unroll
        for (int o = 1; o < 32; o <<= 1) {
            int z = __shfl_up_sync(0xffffffff, y, o);
            if (lane >= o) y += z;
        }
        wsum[lane] = y;
    }
    __syncthreads();
    int warp_excl = (w == 0) ? 0 : wsum[w - 1];
    int texcl = warp_excl + x - s;
    #pragma unroll
    for (int i = 0; i < 10; i++) {
        int idx = base + i;
        if (idx < N_NODES) { int o = texcl + loc[i]; g_off[idx] = o; g_pos[idx] = o; }
    }
    if (t == 1023) g_off[N_NODES] = warp_excl + x;
}

__global__ void scatter_k(const int* __restrict__ src, const int* __restrict__ dst) {
    int e4 = blockIdx.x * blockDim.x + threadIdx.x;
    if (e4 * 4 < N_EDGES) {
        int4 s = ((const int4*)src)[e4];
        int4 d = ((const int4*)dst)[e4];
        g_csr[atomicAdd(&g_pos[d.x], 1)] = s.x;
        g_csr[atomicAdd(&g_pos[d.y], 1)] = s.y;
        g_csr[atomicAdd(&g_pos[d.z], 1)] = s.z;
        g_csr[atomicAdd(&g_pos[d.w], 1)] = s.w;
    }
}

// ---------------- weight prep: Bw[n][0:128]=hi(W[k][n]), [128:256]=lo -----------
template <int DOUT>
__global__ void prep_w_k(const float* __restrict__ Wn, const float* __restrict__ Ws,
                         __half* __restrict__ Bw) {
    int idx = blockIdx.x * 256 + threadIdx.x;       // over NOUT*128
    if (idx >= 2 * DOUT * 128) return;
    int n = idx >> 7, k = idx & 127;
    const float* W = (n < DOUT) ? Wn : Ws;
    int nn = (n < DOUT) ? n : n - DOUT;
    float v = W[(size_t)k * DOUT + nn];
    __half h = __float2half_rn(v);
    __half l = __float2half_rn(v - __half2float(h));
    Bw[(size_t)n * 256 + k]       = h;
    Bw[(size_t)n * 256 + 128 + k] = l;
}

// ---------------- HMMA GEMM: Y = X @ [W_neigh | W_self], hi/lo fp16 split --------
// BM=128, BN=128, full K=128 in smem. 256 threads, warp tile 32x64.
// 3 passes: Ahi*Bhi + Alo*Bhi + Ahi*Blo (fp32 accum; dropped term ~2e-7 rel).
static constexpr int APAD  = 136;                      // halves per row (272 B)
static constexpr int A_HI  = 0;
static constexpr int A_LO  = 128 * APAD * 2;           // 34816
static constexpr int B_HI  = 2 * 128 * APAD * 2;       // 69632
static constexpr int B_LO  = B_HI + 128 * APAD * 2;    // 104448
static constexpr int GEMM_SMEM = B_LO + 128 * APAD * 2; // 139264

template <int DOUT>
__global__ void __launch_bounds__(256, 1)
gemm_mma_k(const float* __restrict__ X, const __half* __restrict__ Bw,
           __half* __restrict__ Yn, float* __restrict__ Ys) {
    extern __shared__ char sm[];
    const uint32_t sb = smem_u32(sm);
    const int tid  = threadIdx.x;
    const int lane = tid & 31;
    const int wid  = tid >> 5;
    const int row0 = blockIdx.x * 128;
    const int col0 = blockIdx.y * 128;

    // ---- A: 128x128 fp32 -> hi/lo fp16, padded rows ----
    #pragma unroll
    for (int i = 0; i < 16; i++) {
        int idx = i * 256 + tid;           // float4 index over 128x32
        int r = idx >> 5, q = idx & 31;    // row, float4 col (k = q*4)
        int grow = row0 + r;
        float4 v = make_float4(0.f, 0.f, 0.f, 0.f);
        if (grow < N_NODES) v = *(const float4*)(X + (size_t)grow * K_DIM + q * 4);
        __half hx = __float2half_rn(v.x), hy = __float2half_rn(v.y);
        __half hz = __float2half_rn(v.z), hw = __float2half_rn(v.w);
        __half2 hp0 = __halves2half2(hx, hy), hp1 = __halves2half2(hz, hw);
        __half2 lp0 = __floats2half2_rn(v.x - __half2float(hx), v.y - __half2float(hy));
        __half2 lp1 = __floats2half2_rn(v.z - __half2float(hz), v.w - __half2float(hw));
        uint32_t off = (uint32_t)(r * APAD + q * 4) * 2;
        uint2 uh; uh.x = *(uint32_t*)&hp0; uh.y = *(uint32_t*)&hp1;
        uint2 ul; ul.x = *(uint32_t*)&lp0; ul.y = *(uint32_t*)&lp1;
        *(uint2*)(sm + A_HI + off) = uh;
        *(uint2*)(sm + A_LO + off) = ul;
    }

    // ---- B: rows [col0, col0+128) of Bw ([n][hi128|lo128]) -> padded smem ----
    #pragma unroll
    for (int i = 0; i < 16; i++) {
        int idx = i * 256 + tid;           // uint4 index over 128x32
        int n = idx >> 5, q = idx & 31;    // row, uint4 chunk (8 halves)
        uint4 v = *(const uint4*)(Bw + (size_t)(col0 + n) * 256 + q * 8);
        int base = (q < 16) ? B_HI : B_LO;
        uint32_t off = (uint32_t)(n * APAD + (q & 15) * 8) * 2;
        *(uint4*)(sm + base + off) = v;
    }
    __syncthreads();

    // ---- MMA mainloop ----
    const int warp_m = wid >> 1;          // 0..3 -> 32-row strip
    const int warp_n = wid & 1;           // 0..1 -> 64-col strip
    const uint32_t lrow = (uint32_t)(lane & 15);
    const uint32_t lcol = (uint32_t)(lane >> 4) * 16;   // byte offset (8 halves)

    float acc[2][8][4];
    #pragma unroll
    for (int a = 0; a < 2; a++)
        #pragma unroll
        for (int b = 0; b < 8; b++)
            #pragma unroll
            for (int c = 0; c < 4; c++) acc[a][b][c] = 0.f;

    #pragma unroll
    for (int p = 0; p < 3; p++) {
        const uint32_t Ab = sb + (p == 1 ? A_LO : A_HI);
        const uint32_t Bb = sb + (p == 2 ? B_LO : B_HI);
        const uint32_t a0addr = Ab + (warp_m * 32 + lrow) * (APAD * 2) + lcol;
        const uint32_t b0addr = Bb + (warp_n * 64 + lrow) * (APAD * 2) + lcol;
        #pragma unroll
        for (int ks = 0; ks < 8; ks++) {
            const uint32_t koff = (uint32_t)ks * 32;     // 16 halves
            uint32_t a0, a1, a2, a3, c0, c1, c2, c3;
            ldsm_x4(a0, a1, a2, a3, a0addr + koff);
            ldsm_x4(c0, c1, c2, c3, a0addr + 16 * (APAD * 2) + koff);
            #pragma unroll
            for (int nb = 0; nb < 4; nb++) {
                // B stored [n][k] row-major -> NON-trans ldmatrix yields the
                // (n = lane>>2, k = 2*(lane&3)+i) fragment mma.row.col needs.
                uint32_t b0, b1, b2, b3;
                ldsm_x4(b0, b1, b2, b3, b0addr + nb * 16 * (APAD * 2) + koff);
                // r0=(n0-7,k0-7) r1=(n8-15,k0-7) r2=(n0-7,k8-15) r3=(n8-15,k8-15)
                mma16816(acc[0][nb * 2],     a0, a1, a2, a3, b0, b2);
                mma16816(acc[0][nb * 2 + 1], a0, a1, a2, a3, b1, b3);
                mma16816(acc[1][nb * 2],     c0, c1, c2, c3, b0, b2);
                mma16816(acc[1][nb * 2 + 1], c0, c1, c2, c3, b1, b3);
            }
        }
    }

    // ---- epilogue: fragments -> Yn (fp16) / Ys (fp32) ----
    #pragma unroll
    for (int mi = 0; mi < 2; mi++) {
        int row_lo = row0 + warp_m * 32 + mi * 16 + (lane >> 2);
        int row_hi = row_lo + 8;
        #pragma unroll
        for (int ni = 0; ni < 8; ni++) {
            float* d = acc[mi][ni];
            int colg = col0 + warp_n * 64 + ni * 8 + (lane & 3) * 2;
            if (colg < DOUT) {
                if (row_lo < N_NODES)
                    *(__half2*)&Yn[(size_t)row_lo * DOUT + colg] = __floats2half2_rn(d[0], d[1]);
                if (row_hi < N_NODES)
                    *(__half2*)&Yn[(size_t)row_hi * DOUT + colg] = __floats2half2_rn(d[2], d[3]);
            } else {
                int c = colg - DOUT;
                if (row_lo < N_NODES)
                    *(float2*)&Ys[(size_t)row_lo * DOUT + c] = make_float2(d[0], d[1]);
                if (row_hi < N_NODES)
                    *(float2*)&Ys[(size_t)row_hi * DOUT + c] = make_float2(d[2], d[3]);
            }
        }
    }
}

// ---------------- aggregate: out = relu?(mean(Yn[csr]) + Ys + bias) -------------
template <int DOUT, bool RELU>
__global__ void aggregate_k(const __half* __restrict__ Yn,
                            const float*  __restrict__ Ys,
                            const float*  __restrict__ bias,
                            float*        __restrict__ out) {
    constexpr int V = DOUT / 32;
    int gw = (blockIdx.x * blockDim.x + threadIdx.x) >> 5;
    if (gw >= N_NODES) return;
    int lane = threadIdx.x & 31;

    int beg = g_off[gw], end = g_off[gw + 1];
    float acc[V];
    #pragma unroll
    for (int v = 0; v < V; v++) acc[v] = 0.f;

    const __half* base = Yn + lane * V;
    int j = beg;
    if constexpr (V == 4) {
        for (; j + 4 <= end; j += 4) {
            int s0 = __ldg(&g_csr[j]);
            int s1 = __ldg(&g_csr[j + 1]);
            int s2 = __ldg(&g_csr[j + 2]);
            int s3 = __ldg(&g_csr[j + 3]);
            uint2 u0 = *(const uint2*)(base + (size_t)s0 * DOUT);
            uint2 u1 = *(const uint2*)(base + (size_t)s1 * DOUT);
            uint2 u2 = *(const uint2*)(base + (size_t)s2 * DOUT);
            uint2 u3 = *(const uint2*)(base + (size_t)s3 * DOUT);
            float2 a, b;
            a = __half22float2(*(__half2*)&u0.x); b = __half22float2(*(__half2*)&u0.y);
            acc[0] += a.x; acc[1] += a.y; acc[2] += b.x; acc[3] += b.y;
            a = __half22float2(*(__half2*)&u1.x); b = __half22float2(*(__half2*)&u1.y);
            acc[0] += a.x; acc[1] += a.y; acc[2] += b.x; acc[3] += b.y;
            a = __half22float2(*(__half2*)&u2.x); b = __half22float2(*(__half2*)&u2.y);
            acc[0] += a.x; acc[1] += a.y; acc[2] += b.x; acc[3] += b.y;
            a = __half22float2(*(__half2*)&u3.x); b = __half22float2(*(__half2*)&u3.y);
            acc[0] += a.x; acc[1] += a.y; acc[2] += b.x; acc[3] += b.y;
        }
        for (; j < end; j++) {
            int s0 = __ldg(&g_csr[j]);
            uint2 u0 = *(const uint2*)(base + (size_t)s0 * DOUT);
            float2 a = __half22float2(*(__half2*)&u0.x);
            float2 b = __half22float2(*(__half2*)&u0.y);
            acc[0] += a.x; acc[1] += a.y; acc[2] += b.x; acc[3] += b.y;
        }
    } else {
        for (; j + 4 <= end; j += 4) {
            int s0 = __ldg(&g_csr[j]);
            int s1 = __ldg(&g_csr[j + 1]);
            int s2 = __ldg(&g_csr[j + 2]);
            int s3 = __ldg(&g_csr[j + 3]);
            unsigned u0 = *(const unsigned*)(base + (size_t)s0 * DOUT);
            unsigned u1 = *(const unsigned*)(base + (size_t)s1 * DOUT);
            unsigned u2 = *(const unsigned*)(base + (size_t)s2 * DOUT);
            unsigned u3 = *(const unsigned*)(base + (size_t)s3 * DOUT);
            float2 a;
            a = __half22float2(*(__half2*)&u0); acc[0] += a.x; acc[1] += a.y;
            a = __half22float2(*(__half2*)&u1); acc[0] += a.x; acc[1] += a.y;
            a = __half22float2(*(__half2*)&u2); acc[0] += a.x; acc[1] += a.y;
            a = __half22float2(*(__half2*)&u3); acc[0] += a.x; acc[1] += a.y;
        }
        for (; j < end; j++) {
            int s0 = __ldg(&g_csr[j]);
            unsigned u0 = *(const unsigned*)(base + (size_t)s0 * DOUT);
            float2 a = __half22float2(*(__half2*)&u0);
            acc[0] += a.x; acc[1] += a.y;
        }
    }

    float inv = 1.0f / fmaxf((float)(end - beg), 1.0f);

    if constexpr (V == 4) {
        float4 s  = *(const float4*)(Ys + (size_t)gw * DOUT + lane * 4);
        float4 bb = *(const float4*)(bias + lane * 4);
        float4 o;
        o.x = acc[0] * inv + s.x + bb.x;
        o.y = acc[1] * inv + s.y + bb.y;
        o.z = acc[2] * inv + s.z + bb.z;
        o.w = acc[3] * inv + s.w + bb.w;
        if (RELU) {
            o.x = fmaxf(o.x, 0.f); o.y = fmaxf(o.y, 0.f);
            o.z = fmaxf(o.z, 0.f); o.w = fmaxf(o.w, 0.f);
        }
        *(float4*)(out + (size_t)gw * DOUT + lane * 4) = o;
    } else {
        float2 s  = *(const float2*)(Ys + (size_t)gw * DOUT + lane * 2);
        float2 bb = *(const float2*)(bias + lane * 2);
        float2 o;
        o.x = acc[0] * inv + s.x + bb.x;
        o.y = acc[1] * inv + s.y + bb.y;
        if (RELU) { o.x = fmaxf(o.x, 0.f); o.y = fmaxf(o.y, 0.f); }
        *(float2*)(out + (size_t)gw * DOUT + lane * 2) = o;
    }
}

// ---------------- launcher -------------------------------------------------------
extern "C" void kernel_launch(void* const* d_in, const int* in_sizes, int n_in,
                              void* d_out, int out_size) {
    const float* inputs  = (const float*)d_in[0];
    const float* W_self0 = (const float*)d_in[1];
    const float* W_nei0  = (const float*)d_in[2];
    const float* b0      = (const float*)d_in[3];
    const float* W_self1 = (const float*)d_in[4];
    const float* W_nei1  = (const float*)d_in[5];
    const float* b1      = (const float*)d_in[6];
    const float* W_self2 = (const float*)d_in[7];
    const float* W_nei2  = (const float*)d_in[8];
    const float* b2      = (const float*)d_in[9];
    const int* edge_src  = (const int*)d_in[10];
    const int* edge_dst  = (const int*)d_in[11];
    float* out = (float*)d_out;

    __half *yn, *bw; float *ys, *h0, *h1; int* deg;
    cudaGetSymbolAddress((void**)&yn,  g_yn);
    cudaGetSymbolAddress((void**)&ys,  g_ys);
    cudaGetSymbolAddress((void**)&h0,  g_h0);
    cudaGetSymbolAddress((void**)&h1,  g_h1);
    cudaGetSymbolAddress((void**)&deg, g_deg);
    cudaGetSymbolAddress((void**)&bw,  g_bw);

    cudaFuncSetAttribute((const void*)gemm_mma_k<128>,
                         cudaFuncAttributeMaxDynamicSharedMemorySize, GEMM_SMEM);
    cudaFuncSetAttribute((const void*)gemm_mma_k<64>,
                         cudaFuncAttributeMaxDynamicSharedMemorySize, GEMM_SMEM);

    // CSR build
    cudaMemsetAsync(deg, 0, N_NODES * sizeof(int));
    hist_k<<<(N_EDGES / 4 + 255) / 256, 256>>>(edge_dst);
    scan_k<<<1, 1024>>>();
    scatter_k<<<(N_EDGES / 4 + 255) / 256, 256>>>(edge_src, edge_dst);

    const int gm = (N_NODES + 127) / 128;        // 79
    const int agg_blocks = (N_NODES + 7) / 8;    // 1250

    // layer 0: 128 -> 128, relu
    prep_w_k<128><<<(256 * 128 + 255) / 256, 256>>>(W_nei0, W_self0, bw);
    gemm_mma_k<128><<<dim3(gm, 2), 256, GEMM_SMEM>>>(inputs, bw, yn, ys);
    aggregate_k<128, true><<<agg_blocks, 256>>>(yn, ys, b0, h0);

    // layer 1: 128 -> 128, relu
    prep_w_k<128><<<(256 * 128 + 255) / 256, 256>>>(W_nei1, W_self1, bw);
    gemm_mma_k<128><<<dim3(gm, 2), 256, GEMM_SMEM>>>(h0, bw, yn, ys);
    aggregate_k<128, true><<<agg_blocks, 256>>>(yn, ys, b1, h1);

    // layer 2: 128 -> 64, no relu
    prep_w_k<64><<<(128 * 128 + 255) / 256, 256>>>(W_nei2, W_self2, bw);
    gemm_mma_k<64><<<dim3(gm, 1), 256, GEMM_SMEM>>>(h1, bw, yn, ys);
    aggregate_k<64, false><<<agg_blocks, 256>>>(yn, ys, b2, out);

    (void)in_sizes; (void)n_in; (void)out_size;
}

// round 6
// speedup vs baseline: 1.5822x; 1.0859x over previous
#include <cuda_runtime.h>
#include <cuda_fp16.h>
#include <cstdint>

#define N_NODES 10000
#define N_EDGES 640000
#define K_DIM   128

// ---------------- scratch -------------------------------------------------------
__device__ __align__(128) int    g_deg[N_NODES];
__device__ __align__(128) int    g_off[N_NODES + 1];
__device__ __align__(128) int    g_pos[N_NODES];
__device__ __align__(128) int    g_csr[N_EDGES];
__device__ __align__(128) __half g_yn[N_NODES * 128];   // neighbor projections (fp16)
__device__ __align__(128) float  g_ys[N_NODES * 128];   // self projections (fp32)
__device__ __align__(128) float  g_h0[N_NODES * 128];
__device__ __align__(128) float  g_h1[N_NODES * 128];
__device__ __align__(128) __half g_bw0[256 * 256];      // layer weights: [NOUT][hi128|lo128]
__device__ __align__(128) __half g_bw1[256 * 256];
__device__ __align__(128) __half g_bw2[128 * 256];

// ---------------- small PTX helpers ----------------------------------------------
__device__ __forceinline__ uint32_t smem_u32(const void* p) {
    uint32_t a;
    asm("{ .reg .u64 t; cvta.to.shared.u64 t, %1; cvt.u32.u64 %0, t; }" : "=r"(a) : "l"(p));
    return a;
}
__device__ __forceinline__ void ldsm_x4(uint32_t& r0, uint32_t& r1, uint32_t& r2,
                                        uint32_t& r3, uint32_t addr) {
    asm volatile("ldmatrix.sync.aligned.m8n8.x4.shared.b16 {%0,%1,%2,%3}, [%4];"
                 : "=r"(r0), "=r"(r1), "=r"(r2), "=r"(r3) : "r"(addr));
}
__device__ __forceinline__ void mma16816(float* d, uint32_t a0, uint32_t a1,
                                         uint32_t a2, uint32_t a3,
                                         uint32_t b0, uint32_t b1) {
    asm volatile(
        "mma.sync.aligned.m16n8k16.row.col.f32.f16.f16.f32 "
        "{%0,%1,%2,%3},{%4,%5,%6,%7},{%8,%9},{%0,%1,%2,%3};"
        : "+f"(d[0]), "+f"(d[1]), "+f"(d[2]), "+f"(d[3])
        : "r"(a0), "r"(a1), "r"(a2), "r"(a3), "r"(b0), "r"(b1));
}
__device__ __forceinline__ uint2 ldg_cg_u2(const void* p) {
    uint2 v;
    asm volatile("ld.global.cg.v2.u32 {%0,%1}, [%2];"
                 : "=r"(v.x), "=r"(v.y) : "l"(p));
    return v;
}
__device__ __forceinline__ unsigned ldg_cg_u1(const void* p) {
    unsigned v;
    asm volatile("ld.global.cg.u32 %0, [%1];" : "=r"(v) : "l"(p));
    return v;
}

// ---------------- fused prep: zero g_deg + build hi/lo weights for all layers ----
// layout per layer L: Bw[n][0:128] = hi(W[k][n]), Bw[n][128:256] = lo
__global__ void prep_all_k(const float* __restrict__ Wn0, const float* __restrict__ Ws0,
                           const float* __restrict__ Wn1, const float* __restrict__ Ws1,
                           const float* __restrict__ Wn2, const float* __restrict__ Ws2) {
    int idx = blockIdx.x * blockDim.x + threadIdx.x;
    if (idx < N_NODES) g_deg[idx] = 0;

    // element space: layer0 [0,32768), layer1 [32768,65536), layer2 [65536,81920)
    if (idx >= 81920) return;
    int layer, base, DOUT;
    const float *Wn, *Ws; __half* Bw;
    if (idx < 32768)      { layer = 0; base = idx;        DOUT = 128; Wn = Wn0; Ws = Ws0; Bw = g_bw0; }
    else if (idx < 65536) { layer = 1; base = idx - 32768; DOUT = 128; Wn = Wn1; Ws = Ws1; Bw = g_bw1; }
    else                  { layer = 2; base = idx - 65536; DOUT = 64;  Wn = Wn2; Ws = Ws2; Bw = g_bw2; }
    (void)layer;
    int n = base >> 7, k = base & 127;                 // n over NOUT=2*DOUT
    const float* W = (n < DOUT) ? Wn : Ws;
    int nn = (n < DOUT) ? n : n - DOUT;
    float v = W[(size_t)k * DOUT + nn];
    __half h = __float2half_rn(v);
    __half l = __float2half_rn(v - __half2float(h));
    Bw[(size_t)n * 256 + k]       = h;
    Bw[(size_t)n * 256 + 128 + k] = l;
}

// ---------------- CSR build ----------------------------------------------------
__global__ void hist_k(const int* __restrict__ dst) {
    int e4 = blockIdx.x * blockDim.x + threadIdx.x;
    if (e4 * 4 < N_EDGES) {
        int4 d = ((const int4*)dst)[e4];
        atomicAdd(&g_deg[d.x], 1); atomicAdd(&g_deg[d.y], 1);
        atomicAdd(&g_deg[d.z], 1); atomicAdd(&g_deg[d.w], 1);
    }
}

__global__ void scan_k() {
    __shared__ int wsum[32];
    int t = threadIdx.x;
    int base = t * 10;
    int loc[10];
    int s = 0;
    #pragma unroll
    for (int i = 0; i < 10; i++) {
        int idx = base + i;
        int v = (idx < N_NODES) ? g_deg[idx] : 0;
        loc[i] = s; s += v;
    }
    int lane = t & 31, w = t >> 5;
    int x = s;
    #pragma unroll
    for (int o = 1; o < 32; o <<= 1) {
        int y = __shfl_up_sync(0xffffffff, x, o);
        if (lane >= o) x += y;
    }
    if (lane == 31) wsum[w] = x;
    __syncthreads();
    if (w == 0) {
        int y = wsum[lane];
        #pragma unroll
        for (int o = 1; o < 32; o <<= 1) {
            int z = __shfl_up_sync(0xffffffff, y, o);
            if (lane >= o) y += z;
        }
        wsum[lane] = y;
    }
    __syncthreads();
    int warp_excl = (w == 0) ? 0 : wsum[w - 1];
    int texcl = warp_excl + x - s;
    #pragma unroll
    for (int i = 0; i < 10; i++) {
        int idx = base + i;
        if (idx < N_NODES) { int o = texcl + loc[i]; g_off[idx] = o; g_pos[idx] = o; }
    }
    if (t == 1023) g_off[N_NODES] = warp_excl + x;
}

__global__ void scatter_k(const int* __restrict__ src, const int* __restrict__ dst) {
    int e4 = blockIdx.x * blockDim.x + threadIdx.x;
    if (e4 * 4 < N_EDGES) {
        int4 s = ((const int4*)src)[e4];
        int4 d = ((const int4*)dst)[e4];
        g_csr[atomicAdd(&g_pos[d.x], 1)] = s.x;
        g_csr[atomicAdd(&g_pos[d.y], 1)] = s.y;
        g_csr[atomicAdd(&g_pos[d.z], 1)] = s.z;
        g_csr[atomicAdd(&g_pos[d.w], 1)] = s.w;
    }
}

// ---------------- HMMA GEMM: Y = X @ [W_neigh | W_self], hi/lo fp16 split --------
static constexpr int APAD  = 136;                      // halves per row (272 B)
static constexpr int A_HI  = 0;
static constexpr int A_LO  = 128 * APAD * 2;
static constexpr int B_HI  = 2 * 128 * APAD * 2;
static constexpr int B_LO  = B_HI + 128 * APAD * 2;
static constexpr int GEMM_SMEM = B_LO + 128 * APAD * 2;

template <int DOUT>
__global__ void __launch_bounds__(256, 1)
gemm_mma_k(const float* __restrict__ X, const __half* __restrict__ Bw,
           __half* __restrict__ Yn, float* __restrict__ Ys) {
    extern __shared__ char sm[];
    const uint32_t sb = smem_u32(sm);
    const int tid  = threadIdx.x;
    const int lane = tid & 31;
    const int wid  = tid >> 5;
    const int row0 = blockIdx.x * 128;
    const int col0 = blockIdx.y * 128;

    // ---- A: 128x128 fp32 -> hi/lo fp16, padded rows ----
    #pragma unroll
    for (int i = 0; i < 16; i++) {
        int idx = i * 256 + tid;
        int r = idx >> 5, q = idx & 31;
        int grow = row0 + r;
        float4 v = make_float4(0.f, 0.f, 0.f, 0.f);
        if (grow < N_NODES) v = *(const float4*)(X + (size_t)grow * K_DIM + q * 4);
        __half hx = __float2half_rn(v.x), hy = __float2half_rn(v.y);
        __half hz = __float2half_rn(v.z), hw = __float2half_rn(v.w);
        __half2 hp0 = __halves2half2(hx, hy), hp1 = __halves2half2(hz, hw);
        __half2 lp0 = __floats2half2_rn(v.x - __half2float(hx), v.y - __half2float(hy));
        __half2 lp1 = __floats2half2_rn(v.z - __half2float(hz), v.w - __half2float(hw));
        uint32_t off = (uint32_t)(r * APAD + q * 4) * 2;
        uint2 uh; uh.x = *(uint32_t*)&hp0; uh.y = *(uint32_t*)&hp1;
        uint2 ul; ul.x = *(uint32_t*)&lp0; ul.y = *(uint32_t*)&lp1;
        *(uint2*)(sm + A_HI + off) = uh;
        *(uint2*)(sm + A_LO + off) = ul;
    }

    // ---- B: rows [col0, col0+128) of Bw ([n][hi128|lo128]) -> padded smem ----
    #pragma unroll
    for (int i = 0; i < 16; i++) {
        int idx = i * 256 + tid;
        int n = idx >> 5, q = idx & 31;
        uint4 v = *(const uint4*)(Bw + (size_t)(col0 + n) * 256 + q * 8);
        int base = (q < 16) ? B_HI : B_LO;
        uint32_t off = (uint32_t)(n * APAD + (q & 15) * 8) * 2;
        *(uint4*)(sm + base + off) = v;
    }
    __syncthreads();

    // ---- MMA mainloop ----
    const int warp_m = wid >> 1;
    const int warp_n = wid & 1;
    const uint32_t lrow = (uint32_t)(lane & 15);
    const uint32_t lcol = (uint32_t)(lane >> 4) * 16;

    float acc[2][8][4];
    #pragma unroll
    for (int a = 0; a < 2; a++)
        #pragma unroll
        for (int b = 0; b < 8; b++)
            #pragma unroll
            for (int c = 0; c < 4; c++) acc[a][b][c] = 0.f;

    #pragma unroll
    for (int p = 0; p < 3; p++) {
        const uint32_t Ab = sb + (p == 1 ? A_LO : A_HI);
        const uint32_t Bb = sb + (p == 2 ? B_LO : B_HI);
        const uint32_t a0addr = Ab + (warp_m * 32 + lrow) * (APAD * 2) + lcol;
        const uint32_t b0addr = Bb + (warp_n * 64 + lrow) * (APAD * 2) + lcol;
        #pragma unroll
        for (int ks = 0; ks < 8; ks++) {
            const uint32_t koff = (uint32_t)ks * 32;
            uint32_t a0, a1, a2, a3, c0, c1, c2, c3;
            ldsm_x4(a0, a1, a2, a3, a0addr + koff);
            ldsm_x4(c0, c1, c2, c3, a0addr + 16 * (APAD * 2) + koff);
            #pragma unroll
            for (int nb = 0; nb < 4; nb++) {
                uint32_t b0, b1, b2, b3;
                ldsm_x4(b0, b1, b2, b3, b0addr + nb * 16 * (APAD * 2) + koff);
                mma16816(acc[0][nb * 2],     a0, a1, a2, a3, b0, b2);
                mma16816(acc[0][nb * 2 + 1], a0, a1, a2, a3, b1, b3);
                mma16816(acc[1][nb * 2],     c0, c1, c2, c3, b0, b2);
                mma16816(acc[1][nb * 2 + 1], c0, c1, c2, c3, b1, b3);
            }
        }
    }

    // ---- epilogue ----
    #pragma unroll
    for (int mi = 0; mi < 2; mi++) {
        int row_lo = row0 + warp_m * 32 + mi * 16 + (lane >> 2);
        int row_hi = row_lo + 8;
        #pragma unroll
        for (int ni = 0; ni < 8; ni++) {
            float* d = acc[mi][ni];
            int colg = col0 + warp_n * 64 + ni * 8 + (lane & 3) * 2;
            if (colg < DOUT) {
                if (row_lo < N_NODES)
                    *(__half2*)&Yn[(size_t)row_lo * DOUT + colg] = __floats2half2_rn(d[0], d[1]);
                if (row_hi < N_NODES)
                    *(__half2*)&Yn[(size_t)row_hi * DOUT + colg] = __floats2half2_rn(d[2], d[3]);
            } else {
                int c = colg - DOUT;
                if (row_lo < N_NODES)
                    *(float2*)&Ys[(size_t)row_lo * DOUT + c] = make_float2(d[0], d[1]);
                if (row_hi < N_NODES)
                    *(float2*)&Ys[(size_t)row_hi * DOUT + c] = make_float2(d[2], d[3]);
            }
        }
    }
}

// ---------------- aggregate: out = relu?(mean(Yn[csr]) + Ys + bias) -------------
// One warp per node; 8-deep gather unroll; .cg loads (skip L1 for gathered rows).
template <int DOUT, bool RELU>
__global__ void aggregate_k(const __half* __restrict__ Yn,
                            const float*  __restrict__ Ys,
                            const float*  __restrict__ bias,
                            float*        __restrict__ out) {
    constexpr int V = DOUT / 32;
    int gw = (blockIdx.x * blockDim.x + threadIdx.x) >> 5;
    if (gw >= N_NODES) return;
    int lane = threadIdx.x & 31;

    int beg = g_off[gw], end = g_off[gw + 1];
    float acc[V];
    #pragma unroll
    for (int v = 0; v < V; v++) acc[v] = 0.f;

    const __half* base = Yn + lane * V;
    int j = beg;
    if constexpr (V == 4) {
        for (; j + 8 <= end; j += 8) {
            int sidx[8];
            #pragma unroll
            for (int u = 0; u < 8; u++) sidx[u] = __ldg(&g_csr[j + u]);
            uint2 uu[8];
            #pragma unroll
            for (int u = 0; u < 8; u++)
                uu[u] = ldg_cg_u2(base + (size_t)sidx[u] * DOUT);
            #pragma unroll
            for (int u = 0; u < 8; u++) {
                float2 a = __half22float2(*(__half2*)&uu[u].x);
                float2 b = __half22float2(*(__half2*)&uu[u].y);
                acc[0] += a.x; acc[1] += a.y; acc[2] += b.x; acc[3] += b.y;
            }
        }
        for (; j < end; j++) {
            int s0 = __ldg(&g_csr[j]);
            uint2 u0 = ldg_cg_u2(base + (size_t)s0 * DOUT);
            float2 a = __half22float2(*(__half2*)&u0.x);
            float2 b = __half22float2(*(__half2*)&u0.y);
            acc[0] += a.x; acc[1] += a.y; acc[2] += b.x; acc[3] += b.y;
        }
    } else {
        for (; j + 8 <= end; j += 8) {
            int sidx[8];
            #pragma unroll
            for (int u = 0; u < 8; u++) sidx[u] = __ldg(&g_csr[j + u]);
            unsigned uu[8];
            #pragma unroll
            for (int u = 0; u < 8; u++)
                uu[u] = ldg_cg_u1(base + (size_t)sidx[u] * DOUT);
            #pragma unroll
            for (int u = 0; u < 8; u++) {
                float2 a = __half22float2(*(__half2*)&uu[u]);
                acc[0] += a.x; acc[1] += a.y;
            }
        }
        for (; j < end; j++) {
            int s0 = __ldg(&g_csr[j]);
            unsigned u0 = ldg_cg_u1(base + (size_t)s0 * DOUT);
            float2 a = __half22float2(*(__half2*)&u0);
            acc[0] += a.x; acc[1] += a.y;
        }
    }

    float inv = 1.0f / fmaxf((float)(end - beg), 1.0f);

    if constexpr (V == 4) {
        float4 s  = *(const float4*)(Ys + (size_t)gw * DOUT + lane * 4);
        float4 bb = *(const float4*)(bias + lane * 4);
        float4 o;
        o.x = acc[0] * inv + s.x + bb.x;
        o.y = acc[1] * inv + s.y + bb.y;
        o.z = acc[2] * inv + s.z + bb.z;
        o.w = acc[3] * inv + s.w + bb.w;
        if (RELU) {
            o.x = fmaxf(o.x, 0.f); o.y = fmaxf(o.y, 0.f);
            o.z = fmaxf(o.z, 0.f); o.w = fmaxf(o.w, 0.f);
        }
        *(float4*)(out + (size_t)gw * DOUT + lane * 4) = o;
    } else {
        float2 s  = *(const float2*)(Ys + (size_t)gw * DOUT + lane * 2);
        float2 bb = *(const float2*)(bias + lane * 2);
        float2 o;
        o.x = acc[0] * inv + s.x + bb.x;
        o.y = acc[1] * inv + s.y + bb.y;
        if (RELU) { o.x = fmaxf(o.x, 0.f); o.y = fmaxf(o.y, 0.f); }
        *(float2*)(out + (size_t)gw * DOUT + lane * 2) = o;
    }
}

// ---------------- launcher -------------------------------------------------------
extern "C" void kernel_launch(void* const* d_in, const int* in_sizes, int n_in,
                              void* d_out, int out_size) {
    const float* inputs  = (const float*)d_in[0];
    const float* W_self0 = (const float*)d_in[1];
    const float* W_nei0  = (const float*)d_in[2];
    const float* b0      = (const float*)d_in[3];
    const float* W_self1 = (const float*)d_in[4];
    const float* W_nei1  = (const float*)d_in[5];
    const float* b1      = (const float*)d_in[6];
    const float* W_self2 = (const float*)d_in[7];
    const float* W_nei2  = (const float*)d_in[8];
    const float* b2      = (const float*)d_in[9];
    const int* edge_src  = (const int*)d_in[10];
    const int* edge_dst  = (const int*)d_in[11];
    float* out = (float*)d_out;

    __half *yn, *bw0, *bw1, *bw2; float *ys, *h0, *h1;
    cudaGetSymbolAddress((void**)&yn,  g_yn);
    cudaGetSymbolAddress((void**)&ys,  g_ys);
    cudaGetSymbolAddress((void**)&h0,  g_h0);
    cudaGetSymbolAddress((void**)&h1,  g_h1);
    cudaGetSymbolAddress((void**)&bw0, g_bw0);
    cudaGetSymbolAddress((void**)&bw1, g_bw1);
    cudaGetSymbolAddress((void**)&bw2, g_bw2);

    cudaFuncSetAttribute((const void*)gemm_mma_k<128>,
                         cudaFuncAttributeMaxDynamicSharedMemorySize, GEMM_SMEM);
    cudaFuncSetAttribute((const void*)gemm_mma_k<64>,
                         cudaFuncAttributeMaxDynamicSharedMemorySize, GEMM_SMEM);

    // prep (zero deg + all 3 layers' hi/lo weights), then CSR build
    prep_all_k<<<(81920 + 255) / 256, 256>>>(W_nei0, W_self0, W_nei1, W_self1, W_nei2, W_self2);
    hist_k<<<(N_EDGES / 4 + 255) / 256, 256>>>(edge_dst);
    scan_k<<<1, 1024>>>();
    scatter_k<<<(N_EDGES / 4 + 255) / 256, 256>>>(edge_src, edge_dst);

    const int gm = (N_NODES + 127) / 128;        // 79
    const int agg_blocks = (N_NODES + 7) / 8;    // 1250

    // layer 0
    gemm_mma_k<128><<<dim3(gm, 2), 256, GEMM_SMEM>>>(inputs, bw0, yn, ys);
    aggregate_k<128, true><<<agg_blocks, 256>>>(yn, ys, b0, h0);
    // layer 1
    gemm_mma_k<128><<<dim3(gm, 2), 256, GEMM_SMEM>>>(h0, bw1, yn, ys);
    aggregate_k<128, true><<<agg_blocks, 256>>>(yn, ys, b1, h1);
    // layer 2
    gemm_mma_k<64><<<dim3(gm, 1), 256, GEMM_SMEM>>>(h1, bw2, yn, ys);
    aggregate_k<64, false><<<agg_blocks, 256>>>(yn, ys, b2, out);

    (void)in_sizes; (void)n_in; (void)out_size;
}

// round 7
// speedup vs baseline: 1.7030x; 1.0763x over previous
#include <cuda_runtime.h>
#include <cuda_fp16.h>
#include <cstdint>

#define N_NODES 10000
#define N_EDGES 640000
#define K_DIM   128

// ---------------- scratch -------------------------------------------------------
__device__ __align__(128) int    g_deg[N_NODES];
__device__ __align__(128) int    g_off[N_NODES + 1];
__device__ __align__(128) int    g_rank[N_EDGES];       // per-edge rank within dst
__device__ __align__(128) int    g_csr[N_EDGES];
__device__ __align__(128) __half g_yn[N_NODES * 128];   // neighbor projections (fp16)
__device__ __align__(128) float  g_ys[N_NODES * 128];   // self projections (fp32)
__device__ __align__(128) float  g_h0[N_NODES * 128];
__device__ __align__(128) float  g_h1[N_NODES * 128];
__device__ __align__(128) __half g_bw0[256 * 256];      // layer weights: [NOUT][hi128|lo128]
__device__ __align__(128) __half g_bw1[256 * 256];
__device__ __align__(128) __half g_bw2[128 * 256];

// ---------------- small PTX helpers ----------------------------------------------
__device__ __forceinline__ uint32_t smem_u32(const void* p) {
    uint32_t a;
    asm("{ .reg .u64 t; cvta.to.shared.u64 t, %1; cvt.u32.u64 %0, t; }" : "=r"(a) : "l"(p));
    return a;
}
__device__ __forceinline__ void ldsm_x4(uint32_t& r0, uint32_t& r1, uint32_t& r2,
                                        uint32_t& r3, uint32_t addr) {
    asm volatile("ldmatrix.sync.aligned.m8n8.x4.shared.b16 {%0,%1,%2,%3}, [%4];"
                 : "=r"(r0), "=r"(r1), "=r"(r2), "=r"(r3) : "r"(addr));
}
__device__ __forceinline__ void mma16816(float* d, uint32_t a0, uint32_t a1,
                                         uint32_t a2, uint32_t a3,
                                         uint32_t b0, uint32_t b1) {
    asm volatile(
        "mma.sync.aligned.m16n8k16.row.col.f32.f16.f16.f32 "
        "{%0,%1,%2,%3},{%4,%5,%6,%7},{%8,%9},{%0,%1,%2,%3};"
        : "+f"(d[0]), "+f"(d[1]), "+f"(d[2]), "+f"(d[3])
        : "r"(a0), "r"(a1), "r"(a2), "r"(a3), "r"(b0), "r"(b1));
}
__device__ __forceinline__ uint2 ldg_cg_u2(const void* p) {
    uint2 v;
    asm volatile("ld.global.cg.v2.u32 {%0,%1}, [%2];"
                 : "=r"(v.x), "=r"(v.y) : "l"(p));
    return v;
}
__device__ __forceinline__ unsigned ldg_cg_u1(const void* p) {
    unsigned v;
    asm volatile("ld.global.cg.u32 %0, [%1];" : "=r"(v) : "l"(p));
    return v;
}

// ---------------- fused prep: zero g_deg + build hi/lo weights for all layers ----
__global__ void prep_all_k(const float* __restrict__ Wn0, const float* __restrict__ Ws0,
                           const float* __restrict__ Wn1, const float* __restrict__ Ws1,
                           const float* __restrict__ Wn2, const float* __restrict__ Ws2) {
    int idx = blockIdx.x * blockDim.x + threadIdx.x;
    if (idx < N_NODES) g_deg[idx] = 0;

    if (idx >= 81920) return;
    int base, DOUT;
    const float *Wn, *Ws; __half* Bw;
    if (idx < 32768)      { base = idx;         DOUT = 128; Wn = Wn0; Ws = Ws0; Bw = g_bw0; }
    else if (idx < 65536) { base = idx - 32768; DOUT = 128; Wn = Wn1; Ws = Ws1; Bw = g_bw1; }
    else                  { base = idx - 65536; DOUT = 64;  Wn = Wn2; Ws = Ws2; Bw = g_bw2; }
    int n = base >> 7, k = base & 127;                 // n over NOUT=2*DOUT
    const float* W = (n < DOUT) ? Wn : Ws;
    int nn = (n < DOUT) ? n : n - DOUT;
    float v = W[(size_t)k * DOUT + nn];
    __half h = __float2half_rn(v);
    __half l = __float2half_rn(v - __half2float(h));
    Bw[(size_t)n * 256 + k]       = h;
    Bw[(size_t)n * 256 + 128 + k] = l;
}

// ---------------- CSR build ----------------------------------------------------
// hist: atomic returns the edge's unique rank within its destination bucket.
__global__ void hist_k(const int* __restrict__ dst) {
    int e4 = blockIdx.x * blockDim.x + threadIdx.x;
    if (e4 * 4 < N_EDGES) {
        int4 d = ((const int4*)dst)[e4];
        int4 r;
        r.x = atomicAdd(&g_deg[d.x], 1);
        r.y = atomicAdd(&g_deg[d.y], 1);
        r.z = atomicAdd(&g_deg[d.z], 1);
        r.w = atomicAdd(&g_deg[d.w], 1);
        ((int4*)g_rank)[e4] = r;
    }
}

__global__ void scan_k() {
    __shared__ int wsum[32];
    int t = threadIdx.x;
    int base = t * 10;
    int loc[10];
    int s = 0;
    #pragma unroll
    for (int i = 0; i < 10; i++) {
        int idx = base + i;
        int v = (idx < N_NODES) ? g_deg[idx] : 0;
        loc[i] = s; s += v;
    }
    int lane = t & 31, w = t >> 5;
    int x = s;
    #pragma unroll
    for (int o = 1; o < 32; o <<= 1) {
        int y = __shfl_up_sync(0xffffffff, x, o);
        if (lane >= o) x += y;
    }
    if (lane == 31) wsum[w] = x;
    __syncthreads();
    if (w == 0) {
        int y = wsum[lane];
        #pragma unroll
        for (int o = 1; o < 32; o <<= 1) {
            int z = __shfl_up_sync(0xffffffff, y, o);
            if (lane >= o) y += z;
        }
        wsum[lane] = y;
    }
    __syncthreads();
    int warp_excl = (w == 0) ? 0 : wsum[w - 1];
    int texcl = warp_excl + x - s;
    #pragma unroll
    for (int i = 0; i < 10; i++) {
        int idx = base + i;
        if (idx < N_NODES) g_off[idx] = texcl + loc[i];
    }
    if (t == 1023) g_off[N_NODES] = warp_excl + x;
}

// scatter: no atomics — position = off[dst] + rank[e].
__global__ void scatter_k(const int* __restrict__ src, const int* __restrict__ dst) {
    int e4 = blockIdx.x * blockDim.x + threadIdx.x;
    if (e4 * 4 < N_EDGES) {
        int4 s = ((const int4*)src)[e4];
        int4 d = ((const int4*)dst)[e4];
        int4 r = ((const int4*)g_rank)[e4];
        g_csr[__ldg(&g_off[d.x]) + r.x] = s.x;
        g_csr[__ldg(&g_off[d.y]) + r.y] = s.y;
        g_csr[__ldg(&g_off[d.z]) + r.z] = s.z;
        g_csr[__ldg(&g_off[d.w]) + r.w] = s.w;
    }
}

// ---------------- HMMA GEMM: Y = X @ [W_neigh | W_self], hi/lo fp16 split --------
static constexpr int APAD  = 136;                      // halves per row (272 B)
static constexpr int A_HI  = 0;
static constexpr int A_LO  = 128 * APAD * 2;
static constexpr int B_HI  = 2 * 128 * APAD * 2;
static constexpr int B_LO  = B_HI + 128 * APAD * 2;
static constexpr int GEMM_SMEM = B_LO + 128 * APAD * 2;

template <int DOUT>
__global__ void __launch_bounds__(256, 1)
gemm_mma_k(const float* __restrict__ X, const __half* __restrict__ Bw,
           __half* __restrict__ Yn, float* __restrict__ Ys) {
    extern __shared__ char sm[];
    const uint32_t sb = smem_u32(sm);
    const int tid  = threadIdx.x;
    const int lane = tid & 31;
    const int wid  = tid >> 5;
    const int row0 = blockIdx.x * 128;
    const int col0 = blockIdx.y * 128;

    // ---- A: 128x128 fp32 -> hi/lo fp16, padded rows ----
    #pragma unroll
    for (int i = 0; i < 16; i++) {
        int idx = i * 256 + tid;
        int r = idx >> 5, q = idx & 31;
        int grow = row0 + r;
        float4 v = make_float4(0.f, 0.f, 0.f, 0.f);
        if (grow < N_NODES) v = *(const float4*)(X + (size_t)grow * K_DIM + q * 4);
        __half hx = __float2half_rn(v.x), hy = __float2half_rn(v.y);
        __half hz = __float2half_rn(v.z), hw = __float2half_rn(v.w);
        __half2 hp0 = __halves2half2(hx, hy), hp1 = __halves2half2(hz, hw);
        __half2 lp0 = __floats2half2_rn(v.x - __half2float(hx), v.y - __half2float(hy));
        __half2 lp1 = __floats2half2_rn(v.z - __half2float(hz), v.w - __half2float(hw));
        uint32_t off = (uint32_t)(r * APAD + q * 4) * 2;
        uint2 uh; uh.x = *(uint32_t*)&hp0; uh.y = *(uint32_t*)&hp1;
        uint2 ul; ul.x = *(uint32_t*)&lp0; ul.y = *(uint32_t*)&lp1;
        *(uint2*)(sm + A_HI + off) = uh;
        *(uint2*)(sm + A_LO + off) = ul;
    }

    // ---- B: rows [col0, col0+128) of Bw ([n][hi128|lo128]) -> padded smem ----
    #pragma unroll
    for (int i = 0; i < 16; i++) {
        int idx = i * 256 + tid;
        int n = idx >> 5, q = idx & 31;
        uint4 v = *(const uint4*)(Bw + (size_t)(col0 + n) * 256 + q * 8);
        int base = (q < 16) ? B_HI : B_LO;
        uint32_t off = (uint32_t)(n * APAD + (q & 15) * 8) * 2;
        *(uint4*)(sm + base + off) = v;
    }
    __syncthreads();

    // ---- MMA mainloop ----
    const int warp_m = wid >> 1;
    const int warp_n = wid & 1;
    const uint32_t lrow = (uint32_t)(lane & 15);
    const uint32_t lcol = (uint32_t)(lane >> 4) * 16;

    float acc[2][8][4];
    #pragma unroll
    for (int a = 0; a < 2; a++)
        #pragma unroll
        for (int b = 0; b < 8; b++)
            #pragma unroll
            for (int c = 0; c < 4; c++) acc[a][b][c] = 0.f;

    #pragma unroll
    for (int p = 0; p < 3; p++) {
        const uint32_t Ab = sb + (p == 1 ? A_LO : A_HI);
        const uint32_t Bb = sb + (p == 2 ? B_LO : B_HI);
        const uint32_t a0addr = Ab + (warp_m * 32 + lrow) * (APAD * 2) + lcol;
        const uint32_t b0addr = Bb + (warp_n * 64 + lrow) * (APAD * 2) + lcol;
        #pragma unroll
        for (int ks = 0; ks < 8; ks++) {
            const uint32_t koff = (uint32_t)ks * 32;
            uint32_t a0, a1, a2, a3, c0, c1, c2, c3;
            ldsm_x4(a0, a1, a2, a3, a0addr + koff);
            ldsm_x4(c0, c1, c2, c3, a0addr + 16 * (APAD * 2) + koff);
            #pragma unroll
            for (int nb = 0; nb < 4; nb++) {
                uint32_t b0, b1, b2, b3;
                ldsm_x4(b0, b1, b2, b3, b0addr + nb * 16 * (APAD * 2) + koff);
                mma16816(acc[0][nb * 2],     a0, a1, a2, a3, b0, b2);
                mma16816(acc[0][nb * 2 + 1], a0, a1, a2, a3, b1, b3);
                mma16816(acc[1][nb * 2],     c0, c1, c2, c3, b0, b2);
                mma16816(acc[1][nb * 2 + 1], c0, c1, c2, c3, b1, b3);
            }
        }
    }

    // ---- epilogue ----
    #pragma unroll
    for (int mi = 0; mi < 2; mi++) {
        int row_lo = row0 + warp_m * 32 + mi * 16 + (lane >> 2);
        int row_hi = row_lo + 8;
        #pragma unroll
        for (int ni = 0; ni < 8; ni++) {
            float* d = acc[mi][ni];
            int colg = col0 + warp_n * 64 + ni * 8 + (lane & 3) * 2;
            if (colg < DOUT) {
                if (row_lo < N_NODES)
                    *(__half2*)&Yn[(size_t)row_lo * DOUT + colg] = __floats2half2_rn(d[0], d[1]);
                if (row_hi < N_NODES)
                    *(__half2*)&Yn[(size_t)row_hi * DOUT + colg] = __floats2half2_rn(d[2], d[3]);
            } else {
                int c = colg - DOUT;
                if (row_lo < N_NODES)
                    *(float2*)&Ys[(size_t)row_lo * DOUT + c] = make_float2(d[0], d[1]);
                if (row_hi < N_NODES)
                    *(float2*)&Ys[(size_t)row_hi * DOUT + c] = make_float2(d[2], d[3]);
            }
        }
    }
}

// ---------------- aggregate: out = relu?(mean(Yn[csr]) + Ys + bias) -------------
template <int DOUT, bool RELU>
__global__ void aggregate_k(const __half* __restrict__ Yn,
                            const float*  __restrict__ Ys,
                            const float*  __restrict__ bias,
                            float*        __restrict__ out) {
    constexpr int V = DOUT / 32;
    int gw = (blockIdx.x * blockDim.x + threadIdx.x) >> 5;
    if (gw >= N_NODES) return;
    int lane = threadIdx.x & 31;

    int beg = g_off[gw], end = g_off[gw + 1];
    float acc[V];
    #pragma unroll
    for (int v = 0; v < V; v++) acc[v] = 0.f;

    const __half* base = Yn + lane * V;
    int j = beg;
    if constexpr (V == 4) {
        for (; j + 8 <= end; j += 8) {
            int sidx[8];
            #pragma unroll
            for (int u = 0; u < 8; u++) sidx[u] = __ldg(&g_csr[j + u]);
            uint2 uu[8];
            #pragma unroll
            for (int u = 0; u < 8; u++)
                uu[u] = ldg_cg_u2(base + (size_t)sidx[u] * DOUT);
            #pragma unroll
            for (int u = 0; u < 8; u++) {
                float2 a = __half22float2(*(__half2*)&uu[u].x);
                float2 b = __half22float2(*(__half2*)&uu[u].y);
                acc[0] += a.x; acc[1] += a.y; acc[2] += b.x; acc[3] += b.y;
            }
        }
        for (; j < end; j++) {
            int s0 = __ldg(&g_csr[j]);
            uint2 u0 = ldg_cg_u2(base + (size_t)s0 * DOUT);
            float2 a = __half22float2(*(__half2*)&u0.x);
            float2 b = __half22float2(*(__half2*)&u0.y);
            acc[0] += a.x; acc[1] += a.y; acc[2] += b.x; acc[3] += b.y;
        }
    } else {
        for (; j + 8 <= end; j += 8) {
            int sidx[8];
            #pragma unroll
            for (int u = 0; u < 8; u++) sidx[u] = __ldg(&g_csr[j + u]);
            unsigned uu[8];
            #pragma unroll
            for (int u = 0; u < 8; u++)
                uu[u] = ldg_cg_u1(base + (size_t)sidx[u] * DOUT);
            #pragma unroll
            for (int u = 0; u < 8; u++) {
                float2 a = __half22float2(*(__half2*)&uu[u]);
                acc[0] += a.x; acc[1] += a.y;
            }
        }
        for (; j < end; j++) {
            int s0 = __ldg(&g_csr[j]);
            unsigned u0 = ldg_cg_u1(base + (size_t)s0 * DOUT);
            float2 a = __half22float2(*(__half2*)&u0);
            acc[0] += a.x; acc[1] += a.y;
        }
    }

    float inv = 1.0f / fmaxf((float)(end - beg), 1.0f);

    if constexpr (V == 4) {
        float4 s  = *(const float4*)(Ys + (size_t)gw * DOUT + lane * 4);
        float4 bb = *(const float4*)(bias + lane * 4);
        float4 o;
        o.x = acc[0] * inv + s.x + bb.x;
        o.y = acc[1] * inv + s.y + bb.y;
        o.z = acc[2] * inv + s.z + bb.z;
        o.w = acc[3] * inv + s.w + bb.w;
        if (RELU) {
            o.x = fmaxf(o.x, 0.f); o.y = fmaxf(o.y, 0.f);
            o.z = fmaxf(o.z, 0.f); o.w = fmaxf(o.w, 0.f);
        }
        *(float4*)(out + (size_t)gw * DOUT + lane * 4) = o;
    } else {
        float2 s  = *(const float2*)(Ys + (size_t)gw * DOUT + lane * 2);
        float2 bb = *(const float2*)(bias + lane * 2);
        float2 o;
        o.x = acc[0] * inv + s.x + bb.x;
        o.y = acc[1] * inv + s.y + bb.y;
        if (RELU) { o.x = fmaxf(o.x, 0.f); o.y = fmaxf(o.y, 0.f); }
        *(float2*)(out + (size_t)gw * DOUT + lane * 2) = o;
    }
}

// ---------------- launcher -------------------------------------------------------
extern "C" void kernel_launch(void* const* d_in, const int* in_sizes, int n_in,
                              void* d_out, int out_size) {
    const float* inputs  = (const float*)d_in[0];
    const float* W_self0 = (const float*)d_in[1];
    const float* W_nei0  = (const float*)d_in[2];
    const float* b0      = (const float*)d_in[3];
    const float* W_self1 = (const float*)d_in[4];
    const float* W_nei1  = (const float*)d_in[5];
    const float* b1      = (const float*)d_in[6];
    const float* W_self2 = (const float*)d_in[7];
    const float* W_nei2  = (const float*)d_in[8];
    const float* b2      = (const float*)d_in[9];
    const int* edge_src  = (const int*)d_in[10];
    const int* edge_dst  = (const int*)d_in[11];
    float* out = (float*)d_out;

    __half *yn, *bw0, *bw1, *bw2; float *ys, *h0, *h1;
    cudaGetSymbolAddress((void**)&yn,  g_yn);
    cudaGetSymbolAddress((void**)&ys,  g_ys);
    cudaGetSymbolAddress((void**)&h0,  g_h0);
    cudaGetSymbolAddress((void**)&h1,  g_h1);
    cudaGetSymbolAddress((void**)&bw0, g_bw0);
    cudaGetSymbolAddress((void**)&bw1, g_bw1);
    cudaGetSymbolAddress((void**)&bw2, g_bw2);

    cudaFuncSetAttribute((const void*)gemm_mma_k<128>,
                         cudaFuncAttributeMaxDynamicSharedMemorySize, GEMM_SMEM);
    cudaFuncSetAttribute((const void*)gemm_mma_k<64>,
                         cudaFuncAttributeMaxDynamicSharedMemorySize, GEMM_SMEM);

    // prep (zero deg + all 3 layers' hi/lo weights), then CSR build
    prep_all_k<<<(81920 + 255) / 256, 256>>>(W_nei0, W_self0, W_nei1, W_self1, W_nei2, W_self2);
    hist_k<<<(N_EDGES / 4 + 255) / 256, 256>>>(edge_dst);
    scan_k<<<1, 1024>>>();
    scatter_k<<<(N_EDGES / 4 + 255) / 256, 256>>>(edge_src, edge_dst);

    const int gm = (N_NODES + 127) / 128;        // 79
    const int agg_blocks = (N_NODES + 7) / 8;    // 1250

    // layer 0
    gemm_mma_k<128><<<dim3(gm, 2), 256, GEMM_SMEM>>>(inputs, bw0, yn, ys);
    aggregate_k<128, true><<<agg_blocks, 256>>>(yn, ys, b0, h0);
    // layer 1
    gemm_mma_k<128><<<dim3(gm, 2), 256, GEMM_SMEM>>>(h0, bw1, yn, ys);
    aggregate_k<128, true><<<agg_blocks, 256>>>(yn, ys, b1, h1);
    // layer 2
    gemm_mma_k<64><<<dim3(gm, 1), 256, GEMM_SMEM>>>(h1, bw2, yn, ys);
    aggregate_k<64, false><<<agg_blocks, 256>>>(yn, ys, b2, out);

    (void)in_sizes; (void)n_in; (void)out_size;
}